// round 6
// baseline (speedup 1.0000x reference)
#include <cuda_runtime.h>
#include <cstddef>

// Problem constants (fixed by setup_inputs)
#define B_   2
#define CV   64
#define CR   20
#define E_   64
#define CO   64
#define MV   100000
#define MR   50000
#define NV   262144      // v2p count per batch
#define NN   65536       // bundles per batch (N / bundle, bundle = 4)
#define TOTN (B_ * NN)   // 131072
#define CELLS (B_ * MR)  // 100000
#define SCAN_BLKS ((CELLS + 255) / 256)   // 391

typedef unsigned long long ull;

// ---------------- scratch (device globals: allocation-free) ----------------
__device__ float g_vT[(size_t)B_ * MV * CV];   // v_feat transposed: (B, Mv, 64)
__device__ float g_rT[(size_t)B_ * MR * CR];   // r_feat transposed: (B, Mr, 20)
__device__ float g_q [(size_t)TOTN * 64];      // q per bundle
__device__ float g_vb[(size_t)TOTN * 64];      // attention-weighted v per bundle
__device__ float g_WkqT[CR * 64];              // [c][f]
__device__ float g_WovT[64 * 64];              // [f][o]
__device__ int   g_iv[(size_t)B_ * NV];        // v indices (int32)
__device__ int   g_ir[(size_t)TOTN];           // r indices (int32)
// CSR build
__device__ int   g_cnt[CELLS];
__device__ int   g_loc[CELLS];
__device__ int   g_off[CELLS];
__device__ int   g_cur[CELLS];
__device__ int   g_bsum[SCAN_BLKS];
__device__ int   g_bpre[SCAN_BLKS];
__device__ int   g_list[TOTN];

// ---------------- zero counts ----------------
__global__ void zero_cnt_kernel() {
    int i = blockIdx.x * blockDim.x + threadIdx.x;
    int stride = gridDim.x * blockDim.x;
    for (; i < CELLS; i += stride) g_cnt[i] = 0;
}

// ---------------- setup: index repack + histogram + weight folds ----------------
#define SETUP_REPACK_BLKS 512
#define SETUP_GRID (SETUP_REPACK_BLKS + 3)

__device__ __forceinline__ bool detect_int64(const int* __restrict__ p) {
    bool i64 = true;
#pragma unroll
    for (int i = 1; i < 32; i += 2) i64 &= (p[i] == 0);
    return i64;
}

__global__ __launch_bounds__(256) void setup_kernel(
    const void* __restrict__ v2p, const void* __restrict__ r2p,
    const float* __restrict__ Wq, const float* __restrict__ Wk,
    const float* __restrict__ Wv, const float* __restrict__ Wo) {
    __shared__ float sA[64 * 64];
    __shared__ float sB[64 * 64];

    int blk = blockIdx.x;
    int tid = threadIdx.x;

    if (blk < SETUP_REPACK_BLKS) {
        const int* pv = (const int*)v2p;
        const int* pr = (const int*)r2p;
        bool v64 = detect_int64(pv);
        bool r64 = detect_int64(pr);
        int t = blk * 256 + tid;
        int stride = SETUP_REPACK_BLKS * 256;
        for (int i = t; i < B_ * NV; i += stride)
            g_iv[i] = v64 ? pv[(size_t)4 * i] : pv[(size_t)2 * i];
        for (int i = t; i < TOTN; i += stride) {
            int ir = r64 ? pr[(size_t)4 * i] : pr[(size_t)2 * i];
            g_ir[i] = ir;
            atomicAdd(&g_cnt[(i >> 16) * MR + ir], 1);
        }
    } else if (blk == SETUP_REPACK_BLKS) {
        for (int i = tid; i < 64 * 64; i += 256) sA[i] = Wk[i];
        for (int i = tid; i < 64 * CR; i += 256) sB[i] = Wq[i];
        __syncthreads();
        for (int i = tid; i < CR * 64; i += 256) {
            int c = i >> 6, f = i & 63;
            float s = 0.f;
#pragma unroll
            for (int e = 0; e < 64; e++) s += sA[e * 64 + f] * sB[e * CR + c];
            g_WkqT[i] = s;  // [c][f]
        }
    } else {
        int half = blk - (SETUP_REPACK_BLKS + 1);  // 0 or 1
        for (int i = tid; i < 64 * 64; i += 256) sA[i] = Wv[i];
        for (int i = tid; i < 64 * 64; i += 256) sB[i] = Wo[i];
        __syncthreads();
        for (int ii = half * 2048 + tid; ii < half * 2048 + 2048; ii += 256) {
            int f = ii >> 6, o = ii & 63;
            float s = 0.f;
#pragma unroll
            for (int e = 0; e < 64; e++) s += sB[o * 64 + e] * sA[e * 64 + f];
            g_WovT[ii] = s;  // [f][o]
        }
    }
}

// ---------------- CSR scan kernels ----------------
__global__ __launch_bounds__(256) void scan_part_kernel() {
    __shared__ int s[256];
    int t = threadIdx.x;
    int cell = blockIdx.x * 256 + t;
    int c = (cell < CELLS) ? g_cnt[cell] : 0;
    s[t] = c;
    __syncthreads();
    for (int off = 1; off < 256; off <<= 1) {
        int add = (t >= off) ? s[t - off] : 0;
        __syncthreads();
        s[t] += add;
        __syncthreads();
    }
    if (cell < CELLS) g_loc[cell] = s[t] - c;
    if (t == 255) g_bsum[blockIdx.x] = s[255];
}

__global__ __launch_bounds__(512) void scan_top_kernel() {
    __shared__ int s[512];
    int t = threadIdx.x;
    int v = (t < SCAN_BLKS) ? g_bsum[t] : 0;
    s[t] = v;
    __syncthreads();
    for (int off = 1; off < 512; off <<= 1) {
        int add = (t >= off) ? s[t - off] : 0;
        __syncthreads();
        s[t] += add;
        __syncthreads();
    }
    if (t < SCAN_BLKS) g_bpre[t] = s[t] - v;
}

__global__ __launch_bounds__(256) void scan_add_kernel() {
    int cell = blockIdx.x * 256 + threadIdx.x;
    if (cell < CELLS) {
        int o = g_loc[cell] + g_bpre[blockIdx.x];
        g_off[cell] = o;
        g_cur[cell] = o;
    }
}

__global__ __launch_bounds__(256) void fill_kernel() {
    int i = blockIdx.x * blockDim.x + threadIdx.x;
    int stride = gridDim.x * blockDim.x;
    for (; i < TOTN; i += stride) {
        int cell = (i >> 16) * MR + g_ir[i];
        int pos = atomicAdd(&g_cur[cell], 1);
        g_list[pos] = i;
    }
}

// ---------------- generic tiled transpose: (B,R,C) -> (B,C,R) ----------------
__global__ void transpose_kernel(const float* __restrict__ in,
                                 float* __restrict__ out, int R, int C) {
    __shared__ float tile[32][33];
    int b = blockIdx.z;
    const float* inb = in + (size_t)b * R * C;
    float* outb = out + (size_t)b * R * C;

    int c = blockIdx.x * 32 + threadIdx.x;
#pragma unroll
    for (int i = threadIdx.y; i < 32; i += 8) {
        int r = blockIdx.y * 32 + i;
        if (r < R && c < C) tile[i][threadIdx.x] = inb[(size_t)r * C + c];
    }
    __syncthreads();
    int r2 = blockIdx.y * 32 + threadIdx.x;
#pragma unroll
    for (int i = threadIdx.y; i < 32; i += 8) {
        int cc = blockIdx.x * 32 + i;
        if (cc < C && r2 < R) outb[(size_t)cc * R + r2] = tile[threadIdx.x][i];
    }
}

// ---------------- q GEMM: g_q[n][f] = sum_c r_pp[n][c] * Wkq[c][f] ----------------
#define QTILE 256
#define QPAD 264
__global__ __launch_bounds__(256) void q_kernel() {
    __shared__ float sW[CR * 64];
    __shared__ float sRT[CR * QPAD];

    int tid = threadIdx.x;
    int tile = blockIdx.x * QTILE;

    for (int i = tid; i < CR * 64; i += 256) sW[i] = g_WkqT[i];
    {
        int n = tile + tid;
        int b = n >> 16;
        int ir = g_ir[n];
        const float4* src = (const float4*)(g_rT + ((size_t)b * MR + ir) * CR);
        float4 r0 = src[0], r1 = src[1], r2 = src[2], r3 = src[3], r4 = src[4];
        float rv[CR] = {r0.x, r0.y, r0.z, r0.w, r1.x, r1.y, r1.z, r1.w,
                        r2.x, r2.y, r2.z, r2.w, r3.x, r3.y, r3.z, r3.w,
                        r4.x, r4.y, r4.z, r4.w};
#pragma unroll
        for (int c = 0; c < CR; c++) sRT[c * QPAD + tid] = rv[c];
    }
    __syncthreads();

    int f0 = (tid & 7) * 8;
    int nl0 = (tid >> 3) * 8;

    ull acc2[4][8];   // p = f-pair, j = bundle
#pragma unroll
    for (int p = 0; p < 4; p++)
#pragma unroll
        for (int j = 0; j < 8; j++) acc2[p][j] = 0ull;

#pragma unroll
    for (int c = 0; c < CR; c++) {
        const float* wrow = sW + c * 64 + f0;
        ull w2[4];
#pragma unroll
        for (int p = 0; p < 4; p++) w2[p] = *(const ull*)(wrow + 2 * p);
        const float* vrow = sRT + c * QPAD + nl0;
        ull v2[8];
#pragma unroll
        for (int j = 0; j < 8; j++) {
            float vj = vrow[j];
            asm("mov.b64 %0, {%1, %1};" : "=l"(v2[j]) : "f"(vj));
        }
#pragma unroll
        for (int p = 0; p < 4; p++)
#pragma unroll
            for (int j = 0; j < 8; j++)
                asm("fma.rn.f32x2 %0, %1, %2, %0;"
                    : "+l"(acc2[p][j]) : "l"(w2[p]), "l"(v2[j]));
    }

#pragma unroll
    for (int j = 0; j < 8; j++) {
        int n = tile + nl0 + j;
        float a[8];
#pragma unroll
        for (int p = 0; p < 4; p++)
            asm("mov.b64 {%0, %1}, %2;" : "=f"(a[2 * p]), "=f"(a[2 * p + 1])
                : "l"(acc2[p][j]));
        float* dst = g_q + (size_t)n * 64 + f0;
        *(float4*)dst = make_float4(a[0], a[1], a[2], a[3]);
        *(float4*)(dst + 4) = make_float4(a[4], a[5], a[6], a[7]);
    }
}

// ---------------- attention kernel (q read from g_q) ----------------
__global__ __launch_bounds__(256) void attn_kernel() {
    const unsigned FULL = 0xffffffffu;
    int gw = (blockIdx.x * 256 + threadIdx.x) >> 5;  // warp id, 4 bundles each
    int lane = threadIdx.x & 31;
    int sub = lane >> 3;
    int fl = lane & 7;

    int n = gw * 4 + sub;
    int b = n >> 16;

    int iv = 0;
    if (lane < 16) iv = g_iv[(size_t)gw * 16 + lane];

    const float4* qp = (const float4*)(g_q + (size_t)n * 64 + fl * 8);
    float4 q0 = qp[0];
    float4 q1 = qp[1];

    const float* vbase = g_vT + (size_t)b * MV * 64;
    float4 v0[4], v1[4];
    float s[4];
#pragma unroll
    for (int m = 0; m < 4; m++) {
        int ivm = __shfl_sync(FULL, iv, sub * 4 + m);
        const float4* vp = (const float4*)(vbase + (size_t)ivm * 64 + fl * 8);
        v0[m] = vp[0];
        v1[m] = vp[1];
        float p = q0.x * v0[m].x + q0.y * v0[m].y + q0.z * v0[m].z + q0.w * v0[m].w
                + q1.x * v1[m].x + q1.y * v1[m].y + q1.z * v1[m].z + q1.w * v1[m].w;
        p += __shfl_xor_sync(FULL, p, 4);
        p += __shfl_xor_sync(FULL, p, 2);
        p += __shfl_xor_sync(FULL, p, 1);
        s[m] = p * 0.125f;  // 1/sqrt(E=64)
    }

    float mx = fmaxf(fmaxf(s[0], s[1]), fmaxf(s[2], s[3]));
    float e0 = __expf(s[0] - mx), e1 = __expf(s[1] - mx);
    float e2 = __expf(s[2] - mx), e3 = __expf(s[3] - mx);
    float inv = 1.0f / (e0 + e1 + e2 + e3);
    e0 *= inv; e1 *= inv; e2 *= inv; e3 *= inv;

    float4 o0, o1;
    o0.x = e0 * v0[0].x + e1 * v0[1].x + e2 * v0[2].x + e3 * v0[3].x;
    o0.y = e0 * v0[0].y + e1 * v0[1].y + e2 * v0[2].y + e3 * v0[3].y;
    o0.z = e0 * v0[0].z + e1 * v0[1].z + e2 * v0[2].z + e3 * v0[3].z;
    o0.w = e0 * v0[0].w + e1 * v0[1].w + e2 * v0[2].w + e3 * v0[3].w;
    o1.x = e0 * v1[0].x + e1 * v1[1].x + e2 * v1[2].x + e3 * v1[3].x;
    o1.y = e0 * v1[0].y + e1 * v1[1].y + e2 * v1[2].y + e3 * v1[3].y;
    o1.z = e0 * v1[0].z + e1 * v1[1].z + e2 * v1[2].z + e3 * v1[3].z;
    o1.w = e0 * v1[0].w + e1 * v1[1].w + e2 * v1[2].w + e3 * v1[3].w;

    float4* op = (float4*)(g_vb + (size_t)n * 64 + fl * 8);
    op[0] = o0;
    op[1] = o1;
}

// ---------------- gather + per-cell sum + GEMM + direct store ----------------
// block: 256 cells (one batch). Phase A: CSR gather-sum of vbar into sVT[f][cl].
// Phase B: out[b][o][m] = sum_f Wov[f][o] * sVT[f][cl], coalesced stores in m.
#define OPAD 260
#define OUT2_FLOATS (64 * 64 + 64 * OPAD)
#define OUT2_BYTES  (OUT2_FLOATS * 4)

__global__ __launch_bounds__(256) void out2_kernel(float* __restrict__ out) {
    extern __shared__ float dsm[];
    float* sW = dsm;                 // [f][o]
    float* sVT = dsm + 64 * 64;      // [f][cl]

    int tid = threadIdx.x;
    int b = blockIdx.y;
    int m0 = blockIdx.x * 256;

    {
        float4* d4 = (float4*)sW;
        const float4* s4 = (const float4*)g_WovT;
        for (int i = tid; i < 1024; i += 256) d4[i] = s4[i];
    }

    int half = tid & 1;
#pragma unroll
    for (int it = 0; it < 2; it++) {
        int cl = (tid >> 1) + it * 128;
        int m = m0 + cl;
        float acc[32];
#pragma unroll
        for (int k = 0; k < 32; k++) acc[k] = 0.f;
        if (m < MR) {
            int cell = b * MR + m;
            int off = g_off[cell];
            int deg = g_cnt[cell];
            for (int d = 0; d < deg; d++) {
                int n = g_list[off + d];
                const float4* src = (const float4*)(g_vb + (size_t)n * 64 + half * 32);
#pragma unroll
                for (int k4 = 0; k4 < 8; k4++) {
                    float4 v = src[k4];
                    acc[k4 * 4 + 0] += v.x;
                    acc[k4 * 4 + 1] += v.y;
                    acc[k4 * 4 + 2] += v.z;
                    acc[k4 * 4 + 3] += v.w;
                }
            }
        }
#pragma unroll
        for (int k = 0; k < 32; k++)
            sVT[(half * 32 + k) * OPAD + cl] = acc[k];
    }
    __syncthreads();

    int o0 = (tid & 7) * 8;
    int ml0 = (tid >> 3) * 8;

    ull acc2[4][8];   // p = m-pair, j = o
#pragma unroll
    for (int p = 0; p < 4; p++)
#pragma unroll
        for (int j = 0; j < 8; j++) acc2[p][j] = 0ull;

#pragma unroll 4
    for (int f = 0; f < 64; f++) {
        const float* wrow = sW + f * 64 + o0;
        float4 w0 = *(const float4*)wrow;
        float4 w1 = *(const float4*)(wrow + 4);
        float w[8] = {w0.x, w0.y, w0.z, w0.w, w1.x, w1.y, w1.z, w1.w};
        ull w2[8];
#pragma unroll
        for (int j = 0; j < 8; j++)
            asm("mov.b64 %0, {%1, %1};" : "=l"(w2[j]) : "f"(w[j]));
        const float* vrow = sVT + f * OPAD + ml0;
        ull v2[4];
#pragma unroll
        for (int p = 0; p < 4; p++) v2[p] = *(const ull*)(vrow + 2 * p);
#pragma unroll
        for (int p = 0; p < 4; p++)
#pragma unroll
            for (int j = 0; j < 8; j++)
                asm("fma.rn.f32x2 %0, %1, %2, %0;"
                    : "+l"(acc2[p][j]) : "l"(v2[p]), "l"(w2[j]));
    }

    if (m0 + ml0 < MR) {
#pragma unroll
        for (int j = 0; j < 8; j++) {
            int o = o0 + j;
            float a[8];
#pragma unroll
            for (int p = 0; p < 4; p++)
                asm("mov.b64 {%0, %1}, %2;" : "=f"(a[2 * p]), "=f"(a[2 * p + 1])
                    : "l"(acc2[p][j]));
            float* dst = out + ((size_t)b * CO + o) * MR + m0 + ml0;
            *(float4*)dst = make_float4(a[0], a[1], a[2], a[3]);
            *(float4*)(dst + 4) = make_float4(a[4], a[5], a[6], a[7]);
        }
    }
}

// ---------------- launch ----------------
extern "C" void kernel_launch(void* const* d_in, const int* in_sizes, int n_in,
                              void* d_out, int out_size) {
    const float* v_feat = (const float*)d_in[0];
    const float* r_feat = (const float*)d_in[1];
    const float* Wq = (const float*)d_in[2];
    const float* Wk = (const float*)d_in[3];
    const float* Wv = (const float*)d_in[4];
    const float* Wo = (const float*)d_in[5];
    const void* v2p = d_in[6];
    const void* r2p = d_in[7];
    float* out = (float*)d_out;

    float *vT, *rT;
    cudaGetSymbolAddress((void**)&vT, g_vT);
    cudaGetSymbolAddress((void**)&rT, g_rT);

    cudaFuncSetAttribute(out2_kernel, cudaFuncAttributeMaxDynamicSharedMemorySize,
                         OUT2_BYTES);

    // CSR + weights + indices
    zero_cnt_kernel<<<98, 1024>>>();
    setup_kernel<<<SETUP_GRID, 256>>>(v2p, r2p, Wq, Wk, Wv, Wo);
    scan_part_kernel<<<SCAN_BLKS, 256>>>();
    scan_top_kernel<<<1, 512>>>();
    scan_add_kernel<<<SCAN_BLKS, 256>>>();
    fill_kernel<<<512, 256>>>();

    // layout transposes
    transpose_kernel<<<dim3((MV + 31) / 32, (CV + 31) / 32, B_), dim3(32, 8)>>>(v_feat, vT, CV, MV);
    transpose_kernel<<<dim3((MR + 31) / 32, (CR + 31) / 32, B_), dim3(32, 8)>>>(r_feat, rT, CR, MR);

    // q GEMM
    q_kernel<<<TOTN / QTILE, 256>>>();

    // attention
    attn_kernel<<<TOTN / 32, 256>>>();

    // per-cell gather-sum + Wov GEMM + direct store (no atomics, no final transpose)
    out2_kernel<<<dim3((MR + 255) / 256, B_), 256, OUT2_BYTES>>>(out);
}

// round 7
// speedup vs baseline: 1.0662x; 1.0662x over previous
#include <cuda_runtime.h>
#include <cstddef>

// Problem constants (fixed by setup_inputs)
#define B_   2
#define CV   64
#define CR   20
#define E_   64
#define CO   64
#define MV   100000
#define MR   50000
#define NV   262144      // v2p count per batch
#define NN   65536       // bundles per batch (N / bundle, bundle = 4)
#define TOTN (B_ * NN)   // 131072
#define CELLS (B_ * MR)  // 100000

typedef unsigned long long ull;

// ---------------- scratch (device globals: allocation-free) ----------------
__device__ float g_vT[(size_t)B_ * MV * CV];    // v_feat transposed: (B, Mv, 64)
__device__ float g_rT[(size_t)B_ * MR * CR];    // r_feat transposed: (B, Mr, 20)
__device__ float g_q [(size_t)TOTN * 64];       // q per bundle
__device__ float g_vbar[(size_t)CELLS * 64];    // per-cell summed vbar (RED target)
__device__ float g_WkqT[CR * 64];               // [c][f]
__device__ float g_WovT[64 * 64];               // [f][o]
__device__ int   g_iv[(size_t)B_ * NV];         // v indices (int32)
__device__ int   g_ir[(size_t)TOTN];            // r indices (int32)

// ---------------- setup: repack + zero vbar + weight folds ----------------
#define SETUP_REPACK_BLKS 512
#define SETUP_ZERO_BLKS   256
#define SETUP_GRID (SETUP_REPACK_BLKS + SETUP_ZERO_BLKS + 3)

__device__ __forceinline__ bool detect_int64(const int* __restrict__ p) {
    bool i64 = true;
#pragma unroll
    for (int i = 1; i < 32; i += 2) i64 &= (p[i] == 0);
    return i64;
}

__global__ __launch_bounds__(256) void setup_kernel(
    const void* __restrict__ v2p, const void* __restrict__ r2p,
    const float* __restrict__ Wq, const float* __restrict__ Wk,
    const float* __restrict__ Wv, const float* __restrict__ Wo) {
    __shared__ float sA[64 * 64];
    __shared__ float sB[64 * 64];

    int blk = blockIdx.x;
    int tid = threadIdx.x;

    if (blk < SETUP_REPACK_BLKS) {
        const int* pv = (const int*)v2p;
        const int* pr = (const int*)r2p;
        bool v64 = detect_int64(pv);
        bool r64 = detect_int64(pr);
        int t = blk * 256 + tid;
        int stride = SETUP_REPACK_BLKS * 256;
        for (int i = t; i < B_ * NV; i += stride)
            g_iv[i] = v64 ? pv[(size_t)4 * i] : pv[(size_t)2 * i];
        for (int i = t; i < TOTN; i += stride)
            g_ir[i] = r64 ? pr[(size_t)4 * i] : pr[(size_t)2 * i];
    } else if (blk < SETUP_REPACK_BLKS + SETUP_ZERO_BLKS) {
        // zero the RED accumulator
        float4* p = (float4*)g_vbar;
        int n4 = (CELLS * 64) / 4;
        int t = (blk - SETUP_REPACK_BLKS) * 256 + tid;
        int stride = SETUP_ZERO_BLKS * 256;
        float4 z = make_float4(0.f, 0.f, 0.f, 0.f);
        for (int i = t; i < n4; i += stride) p[i] = z;
    } else if (blk == SETUP_REPACK_BLKS + SETUP_ZERO_BLKS) {
        for (int i = tid; i < 64 * 64; i += 256) sA[i] = Wk[i];
        for (int i = tid; i < 64 * CR; i += 256) sB[i] = Wq[i];
        __syncthreads();
        for (int i = tid; i < CR * 64; i += 256) {
            int c = i >> 6, f = i & 63;
            float s = 0.f;
#pragma unroll
            for (int e = 0; e < 64; e++) s += sA[e * 64 + f] * sB[e * CR + c];
            g_WkqT[i] = s;  // [c][f]
        }
    } else {
        int half = blk - (SETUP_REPACK_BLKS + SETUP_ZERO_BLKS + 1);  // 0 or 1
        for (int i = tid; i < 64 * 64; i += 256) sA[i] = Wv[i];
        for (int i = tid; i < 64 * 64; i += 256) sB[i] = Wo[i];
        __syncthreads();
        for (int ii = half * 2048 + tid; ii < half * 2048 + 2048; ii += 256) {
            int f = ii >> 6, o = ii & 63;
            float s = 0.f;
#pragma unroll
            for (int e = 0; e < 64; e++) s += sB[o * 64 + e] * sA[e * 64 + f];
            g_WovT[ii] = s;  // [f][o]
        }
    }
}

// ---------------- generic tiled transpose: (B,R,C) -> (B,C,R) ----------------
__global__ void transpose_kernel(const float* __restrict__ in,
                                 float* __restrict__ out, int R, int C) {
    __shared__ float tile[32][33];
    int b = blockIdx.z;
    const float* inb = in + (size_t)b * R * C;
    float* outb = out + (size_t)b * R * C;

    int c = blockIdx.x * 32 + threadIdx.x;
#pragma unroll
    for (int i = threadIdx.y; i < 32; i += 8) {
        int r = blockIdx.y * 32 + i;
        if (r < R && c < C) tile[i][threadIdx.x] = inb[(size_t)r * C + c];
    }
    __syncthreads();
    int r2 = blockIdx.y * 32 + threadIdx.x;
#pragma unroll
    for (int i = threadIdx.y; i < 32; i += 8) {
        int cc = blockIdx.x * 32 + i;
        if (cc < C && r2 < R) outb[(size_t)cc * R + r2] = tile[threadIdx.x][i];
    }
}

// ---------------- q GEMM: g_q[n][f] = sum_c r_pp[n][c] * Wkq[c][f] ----------------
#define QTILE 256
#define QPAD 264
__global__ __launch_bounds__(256) void q_kernel() {
    __shared__ float sW[CR * 64];
    __shared__ float sRT[CR * QPAD];

    int tid = threadIdx.x;
    int tile = blockIdx.x * QTILE;

    for (int i = tid; i < CR * 64; i += 256) sW[i] = g_WkqT[i];
    {
        int n = tile + tid;
        int b = n >> 16;
        int ir = g_ir[n];
        const float4* src = (const float4*)(g_rT + ((size_t)b * MR + ir) * CR);
        float4 r0 = src[0], r1 = src[1], r2 = src[2], r3 = src[3], r4 = src[4];
        float rv[CR] = {r0.x, r0.y, r0.z, r0.w, r1.x, r1.y, r1.z, r1.w,
                        r2.x, r2.y, r2.z, r2.w, r3.x, r3.y, r3.z, r3.w,
                        r4.x, r4.y, r4.z, r4.w};
#pragma unroll
        for (int c = 0; c < CR; c++) sRT[c * QPAD + tid] = rv[c];
    }
    __syncthreads();

    int f0 = (tid & 7) * 8;
    int nl0 = (tid >> 3) * 8;

    ull acc2[4][8];   // p = f-pair, j = bundle
#pragma unroll
    for (int p = 0; p < 4; p++)
#pragma unroll
        for (int j = 0; j < 8; j++) acc2[p][j] = 0ull;

#pragma unroll
    for (int c = 0; c < CR; c++) {
        const float* wrow = sW + c * 64 + f0;
        ull w2[4];
#pragma unroll
        for (int p = 0; p < 4; p++) w2[p] = *(const ull*)(wrow + 2 * p);
        const float* vrow = sRT + c * QPAD + nl0;
        ull v2[8];
#pragma unroll
        for (int j = 0; j < 8; j++) {
            float vj = vrow[j];
            asm("mov.b64 %0, {%1, %1};" : "=l"(v2[j]) : "f"(vj));
        }
#pragma unroll
        for (int p = 0; p < 4; p++)
#pragma unroll
            for (int j = 0; j < 8; j++)
                asm("fma.rn.f32x2 %0, %1, %2, %0;"
                    : "+l"(acc2[p][j]) : "l"(w2[p]), "l"(v2[j]));
    }

#pragma unroll
    for (int j = 0; j < 8; j++) {
        int n = tile + nl0 + j;
        float a[8];
#pragma unroll
        for (int p = 0; p < 4; p++)
            asm("mov.b64 {%0, %1}, %2;" : "=f"(a[2 * p]), "=f"(a[2 * p + 1])
                : "l"(acc2[p][j]));
        float* dst = g_q + (size_t)n * 64 + f0;
        *(float4*)dst = make_float4(a[0], a[1], a[2], a[3]);
        *(float4*)(dst + 4) = make_float4(a[4], a[5], a[6], a[7]);
    }
}

// ---------------- attention kernel: gather v, softmax, RED into g_vbar ----------------
__global__ __launch_bounds__(256) void attn_kernel() {
    const unsigned FULL = 0xffffffffu;
    int gw = (blockIdx.x * 256 + threadIdx.x) >> 5;  // warp id, 4 bundles each
    int lane = threadIdx.x & 31;
    int sub = lane >> 3;
    int fl = lane & 7;

    int n = gw * 4 + sub;
    int b = n >> 16;

    // lanes 0..15: iv (16 values); lanes 16..19: ir (4 values)
    int ldv = 0;
    if (lane < 16) ldv = g_iv[(size_t)gw * 16 + lane];
    else if (lane < 20) ldv = g_ir[gw * 4 + (lane - 16)];

    const float4* qp = (const float4*)(g_q + (size_t)n * 64 + fl * 8);
    float4 q0 = qp[0];
    float4 q1 = qp[1];

    const float* vbase = g_vT + (size_t)b * MV * 64;
    float4 v0[4], v1[4];
    float s[4];
#pragma unroll
    for (int m = 0; m < 4; m++) {
        int ivm = __shfl_sync(FULL, ldv, sub * 4 + m);
        const float4* vp = (const float4*)(vbase + (size_t)ivm * 64 + fl * 8);
        v0[m] = vp[0];
        v1[m] = vp[1];
        float p = q0.x * v0[m].x + q0.y * v0[m].y + q0.z * v0[m].z + q0.w * v0[m].w
                + q1.x * v1[m].x + q1.y * v1[m].y + q1.z * v1[m].z + q1.w * v1[m].w;
        p += __shfl_xor_sync(FULL, p, 4);
        p += __shfl_xor_sync(FULL, p, 2);
        p += __shfl_xor_sync(FULL, p, 1);
        s[m] = p * 0.125f;  // 1/sqrt(E=64)
    }

    int ir_n = __shfl_sync(FULL, ldv, 16 + sub);

    float mx = fmaxf(fmaxf(s[0], s[1]), fmaxf(s[2], s[3]));
    float e0 = __expf(s[0] - mx), e1 = __expf(s[1] - mx);
    float e2 = __expf(s[2] - mx), e3 = __expf(s[3] - mx);
    float inv = 1.0f / (e0 + e1 + e2 + e3);
    e0 *= inv; e1 *= inv; e2 *= inv; e3 *= inv;

    float4 o0, o1;
    o0.x = e0 * v0[0].x + e1 * v0[1].x + e2 * v0[2].x + e3 * v0[3].x;
    o0.y = e0 * v0[0].y + e1 * v0[1].y + e2 * v0[2].y + e3 * v0[3].y;
    o0.z = e0 * v0[0].z + e1 * v0[1].z + e2 * v0[2].z + e3 * v0[3].z;
    o0.w = e0 * v0[0].w + e1 * v0[1].w + e2 * v0[2].w + e3 * v0[3].w;
    o1.x = e0 * v1[0].x + e1 * v1[1].x + e2 * v1[2].x + e3 * v1[3].x;
    o1.y = e0 * v1[0].y + e1 * v1[1].y + e2 * v1[2].y + e3 * v1[3].y;
    o1.z = e0 * v1[0].z + e1 * v1[1].z + e2 * v1[2].z + e3 * v1[3].z;
    o1.w = e0 * v1[0].w + e1 * v1[1].w + e2 * v1[2].w + e3 * v1[3].w;

    // reduce directly into per-cell accumulator (pre-GEMM scatter)
    float* dst = g_vbar + ((size_t)b * MR + ir_n) * 64 + fl * 8;
    asm volatile("red.global.add.v4.f32 [%0], {%1, %2, %3, %4};"
                 :: "l"(dst), "f"(o0.x), "f"(o0.y), "f"(o0.z), "f"(o0.w) : "memory");
    asm volatile("red.global.add.v4.f32 [%0], {%1, %2, %3, %4};"
                 :: "l"(dst + 4), "f"(o1.x), "f"(o1.y), "f"(o1.z), "f"(o1.w) : "memory");
}

// ---------------- dense output GEMM: out[b][o][m] = sum_f Wov[f][o] * vbar[m][f] ----------------
#define OPAD 260
#define OUT3_FLOATS (64 * 64 + 64 * OPAD)
#define OUT3_BYTES  (OUT3_FLOATS * 4)

__global__ __launch_bounds__(256) void out3_kernel(float* __restrict__ out) {
    extern __shared__ float dsm[];
    float* sW = dsm;                 // [f][o]
    float* sVT = dsm + 64 * 64;      // [f][cl]

    int tid = threadIdx.x;
    int b = blockIdx.y;
    int m0 = blockIdx.x * 256;

    {
        float4* d4 = (float4*)sW;
        const float4* s4 = (const float4*)g_WovT;
        for (int i = tid; i < 1024; i += 256) d4[i] = s4[i];
    }
    // coalesced load of 256 cells' vbar, transposed into sVT[f][cl]
    for (int i = tid; i < 256 * 16; i += 256) {
        int cl = i >> 4;
        int c4 = i & 15;
        int m = m0 + cl;
        float4 v = make_float4(0.f, 0.f, 0.f, 0.f);
        if (m < MR)
            v = *(const float4*)(g_vbar + ((size_t)b * MR + m) * 64 + c4 * 4);
        int f = c4 * 4;
        sVT[(f + 0) * OPAD + cl] = v.x;
        sVT[(f + 1) * OPAD + cl] = v.y;
        sVT[(f + 2) * OPAD + cl] = v.z;
        sVT[(f + 3) * OPAD + cl] = v.w;
    }
    __syncthreads();

    int o0 = (tid & 7) * 8;
    int ml0 = (tid >> 3) * 8;

    ull acc2[4][8];   // p = m-pair, j = o
#pragma unroll
    for (int p = 0; p < 4; p++)
#pragma unroll
        for (int j = 0; j < 8; j++) acc2[p][j] = 0ull;

#pragma unroll 4
    for (int f = 0; f < 64; f++) {
        const float* wrow = sW + f * 64 + o0;
        float4 w0 = *(const float4*)wrow;
        float4 w1 = *(const float4*)(wrow + 4);
        float w[8] = {w0.x, w0.y, w0.z, w0.w, w1.x, w1.y, w1.z, w1.w};
        ull w2[8];
#pragma unroll
        for (int j = 0; j < 8; j++)
            asm("mov.b64 %0, {%1, %1};" : "=l"(w2[j]) : "f"(w[j]));
        const float* vrow = sVT + f * OPAD + ml0;
        ull v2[4];
#pragma unroll
        for (int p = 0; p < 4; p++) v2[p] = *(const ull*)(vrow + 2 * p);
#pragma unroll
        for (int p = 0; p < 4; p++)
#pragma unroll
            for (int j = 0; j < 8; j++)
                asm("fma.rn.f32x2 %0, %1, %2, %0;"
                    : "+l"(acc2[p][j]) : "l"(v2[p]), "l"(w2[j]));
    }

    if (m0 + ml0 < MR) {
#pragma unroll
        for (int j = 0; j < 8; j++) {
            int o = o0 + j;
            float a[8];
#pragma unroll
            for (int p = 0; p < 4; p++)
                asm("mov.b64 {%0, %1}, %2;" : "=f"(a[2 * p]), "=f"(a[2 * p + 1])
                    : "l"(acc2[p][j]));
            float* dst = out + ((size_t)b * CO + o) * MR + m0 + ml0;
            *(float4*)dst = make_float4(a[0], a[1], a[2], a[3]);
            *(float4*)(dst + 4) = make_float4(a[4], a[5], a[6], a[7]);
        }
    }
}

// ---------------- launch ----------------
extern "C" void kernel_launch(void* const* d_in, const int* in_sizes, int n_in,
                              void* d_out, int out_size) {
    const float* v_feat = (const float*)d_in[0];
    const float* r_feat = (const float*)d_in[1];
    const float* Wq = (const float*)d_in[2];
    const float* Wk = (const float*)d_in[3];
    const float* Wv = (const float*)d_in[4];
    const float* Wo = (const float*)d_in[5];
    const void* v2p = d_in[6];
    const void* r2p = d_in[7];
    float* out = (float*)d_out;

    float *vT, *rT;
    cudaGetSymbolAddress((void**)&vT, g_vT);
    cudaGetSymbolAddress((void**)&rT, g_rT);

    cudaFuncSetAttribute(out3_kernel, cudaFuncAttributeMaxDynamicSharedMemorySize,
                         OUT3_BYTES);

    // 1) setup: repack indices + zero vbar accumulator + fold weights
    setup_kernel<<<SETUP_GRID, 256>>>(v2p, r2p, Wq, Wk, Wv, Wo);

    // 2) layout transposes
    transpose_kernel<<<dim3((MV + 31) / 32, (CV + 31) / 32, B_), dim3(32, 8)>>>(v_feat, vT, CV, MV);
    transpose_kernel<<<dim3((MR + 31) / 32, (CR + 31) / 32, B_), dim3(32, 8)>>>(r_feat, rT, CR, MR);

    // 3) q GEMM
    q_kernel<<<TOTN / QTILE, 256>>>();

    // 4) attention + pre-GEMM scatter (RED into g_vbar)
    attn_kernel<<<TOTN / 32, 256>>>();

    // 5) dense Wov GEMM + direct store into final layout
    out3_kernel<<<dim3((MR + 255) / 256, B_), 256, OUT3_BYTES>>>(out);
}